// round 3
// baseline (speedup 1.0000x reference)
#include <cuda_runtime.h>
#include <cstdint>

typedef unsigned long long u64;

#define Bn   16
#define R    360
#define RPAD 384   // padded row length (float2 units) for u/v scratch

// Scratch: u2[b][dpair k][i] = (u[i][2k], u[i][2k+1]) packed fp32x2; same for v (v includes +b_out)
// __device__ globals are zero-initialized: pad region [360,384) stays 0 and is harmless.
__device__ u64 g_u2[Bn * 32 * RPAD];
__device__ u64 g_v2[Bn * 32 * RPAD];

// ---------- packed fp32x2 helpers (sm_100+) ----------
__device__ __forceinline__ u64 pack2(float x, float y) {
    u64 d; asm("mov.b64 %0, {%1, %2};" : "=l"(d) : "f"(x), "f"(y)); return d;
}
__device__ __forceinline__ void unpack2(u64 a, float &x, float &y) {
    asm("mov.b64 {%0, %1}, %2;" : "=f"(x), "=f"(y) : "l"(a));
}
__device__ __forceinline__ u64 fadd2(u64 a, u64 b) {
    u64 d; asm("add.rn.f32x2 %0, %1, %2;" : "=l"(d) : "l"(a), "l"(b)); return d;
}
__device__ __forceinline__ void ffma2(u64 &d, u64 a, u64 b) {
    asm("fma.rn.f32x2 %0, %1, %2, %0;" : "+l"(d) : "l"(a), "l"(b));
}
__device__ __forceinline__ u64 relu2(u64 a) {
    float lo, hi; unpack2(a, lo, hi);
    lo = fmaxf(lo, 0.0f); hi = fmaxf(hi, 0.0f);
    return pack2(lo, hi);
}

// ============================================================================
// Kernel 1: u = x @ Wout[0:64], v = x @ Wout[64:128] + b_out
// [5760 x 64] @ [64 x 128], fp32x2-packed over k-pairs, 48 rows/block -> 120 blocks.
// Stores transposed: g_u2[b][k][i] = (u[i][2k], u[i][2k+1]).
// ============================================================================
#define K1_ROWS 48

__global__ __launch_bounds__(256, 2) void k1_uv(
    const float* __restrict__ x,      // [5760][64]
    const float* __restrict__ Wout,   // [128][64]
    const float* __restrict__ bout)   // [64]
{
    __shared__ u64 xs[32][K1_ROWS];  // [kpair][row]
    __shared__ u64 Wu[32][64];       // [kpair][d]
    __shared__ u64 Wv[32][64];

    const int t = threadIdx.x;
    const int row0 = blockIdx.x * K1_ROWS;

    // Fill xs
    {
        const u64* x2 = (const u64*)x;   // float2 view (32 per row)
        #pragma unroll
        for (int idx = t; idx < 32 * K1_ROWS; idx += 256) {
            const int p = idx / K1_ROWS;
            const int i = idx - p * K1_ROWS;
            xs[p][i] = x2[(row0 + i) * 32 + p];
        }
    }
    // Fill Wu / Wv (coalesced on d)
    {
        const int c = t & 63, p0 = t >> 6;
        #pragma unroll
        for (int p = p0; p < 32; p += 4) {
            Wu[p][c] = pack2(Wout[(2 * p) * 64 + c],      Wout[(2 * p + 1) * 64 + c]);
            Wv[p][c] = pack2(Wout[(64 + 2 * p) * 64 + c], Wout[(65 + 2 * p) * 64 + c]);
        }
    }
    __syncthreads();

    // Thread tile: 3 rows (stride-16) x 8 cols
    const int rt = t & 15;
    const int ct = t >> 4;            // ct<8 => u cols, ct>=8 => v cols
    const int ccol = (ct & 7) * 8;
    const bool isv = (ct >= 8);
    const u64 (*Ws)[64] = isv ? Wv : Wu;

    u64 acc[3][8];
    #pragma unroll
    for (int ii = 0; ii < 3; ii++)
        #pragma unroll
        for (int j = 0; j < 8; j++) acc[ii][j] = 0ull;

    #pragma unroll 8
    for (int p = 0; p < 32; p++) {
        u64 xv[3];
        #pragma unroll
        for (int ii = 0; ii < 3; ii++) xv[ii] = xs[p][rt + 16 * ii];
        u64 wv[8];
        #pragma unroll
        for (int q = 0; q < 4; q++) {
            ulonglong2 w2 = *(const ulonglong2*)&Ws[p][ccol + 2 * q];
            wv[2 * q] = w2.x; wv[2 * q + 1] = w2.y;
        }
        #pragma unroll
        for (int ii = 0; ii < 3; ii++)
            #pragma unroll
            for (int j = 0; j < 8; j++)
                ffma2(acc[ii][j], xv[ii], wv[j]);   // lo: even-k partial, hi: odd-k partial
    }

    // Epilogue: reduce lo+hi, add b_out for v-half, store transposed pairs
    u64* gdst = isv ? g_v2 : g_u2;
    #pragma unroll
    for (int ii = 0; ii < 3; ii++) {
        const int grow = row0 + rt + 16 * ii;     // [0, 5760)
        const int bb = grow / 360;
        const int i = grow - bb * 360;
        #pragma unroll
        for (int j = 0; j < 8; j += 2) {
            float l0, h0, l1, h1;
            unpack2(acc[ii][j], l0, h0);
            unpack2(acc[ii][j + 1], l1, h1);
            float v0 = l0 + h0, v1 = l1 + h1;
            const int dd = ccol + j;
            if (isv) { v0 += __ldg(&bout[dd]); v1 += __ldg(&bout[dd + 1]); }
            gdst[(bb * 32 + (dd >> 1)) * RPAD + i] = pack2(v0, v1);
        }
    }
}

// ============================================================================
// Kernel 2: out[b,rec,send] = relu( sum_d Wcat[d]*relu(u[send,d]+v[rec,d]) + b_cat )
// Tile: 48 rec x 64 send per block, 256 threads, 4 send x 3 rec per thread.
// Reg diet (acc 24 + uu 8 + vv 6 + w 2) targets <=51 regs -> 5 CTAs/SM = 40 warps.
// ============================================================================
__global__ __launch_bounds__(256, 5) void k2_pair(
    const float* __restrict__ Wcat,   // [64]
    const float* __restrict__ bcat,   // [1]
    float* __restrict__ out)          // [16*360*360]
{
    __shared__ u64 Us[32][64];    // [dpair][send]
    __shared__ u64 Vs[32][48];    // [dpair][rec]
    __shared__ u64 Ww[32];        // packed Wcat pairs

    const int t = threadIdx.x;
    const int b  = blockIdx.z;
    const int s0 = blockIdx.x * 64;
    const int r0 = blockIdx.y * 48;

    // Fill tiles (coalesced; pad region reads zeros)
    {
        const int c = t & 63, k0 = t >> 6;
        const u64* gu = g_u2 + b * 32 * RPAD + s0 + c;
        #pragma unroll
        for (int k = k0; k < 32; k += 4) Us[k][c] = gu[k * RPAD];

        const u64* gvb = g_v2 + b * 32 * RPAD + r0;
        #pragma unroll
        for (int idx = t; idx < 32 * 48; idx += 256) {
            const int k = idx / 48;
            const int c2 = idx - k * 48;
            Vs[k][c2] = gvb[k * RPAD + c2];
        }
        if (t < 32) Ww[t] = ((const u64*)Wcat)[t];
    }
    __syncthreads();

    const int sx = (t & 15) * 4;   // send base (0..60)
    const int ry = (t >> 4) * 3;   // rec base  (0..45)

    u64 acc[3][4];
    #pragma unroll
    for (int i = 0; i < 3; i++)
        #pragma unroll
        for (int j = 0; j < 4; j++) acc[i][j] = 0ull;

    #pragma unroll 8
    for (int k = 0; k < 32; k++) {
        const u64 w2 = Ww[k];   // LDS broadcast
        u64 uu[4];
        {
            ulonglong2 ua = *(const ulonglong2*)&Us[k][sx];
            ulonglong2 ub = *(const ulonglong2*)&Us[k][sx + 2];
            uu[0] = ua.x; uu[1] = ua.y; uu[2] = ub.x; uu[3] = ub.y;
        }
        u64 vv[3];
        vv[0] = Vs[k][ry];
        vv[1] = Vs[k][ry + 1];
        vv[2] = Vs[k][ry + 2];
        #pragma unroll
        for (int i = 0; i < 3; i++)
            #pragma unroll
            for (int j = 0; j < 4; j++) {
                u64 tt = relu2(fadd2(uu[j], vv[i]));
                ffma2(acc[i][j], tt, w2);
            }
    }

    // Epilogue: lo+hi + b_cat, relu, float4 stores (guard send + rec pads)
    const float bc = __ldg(bcat);
    const int s = s0 + sx;
    if (s < R) {
        #pragma unroll
        for (int i = 0; i < 3; i++) {
            const int rec = r0 + ry + i;
            if (rec < R) {
                float4 o;
                float lx, hx;
                unpack2(acc[i][0], lx, hx); o.x = fmaxf(lx + hx + bc, 0.0f);
                unpack2(acc[i][1], lx, hx); o.y = fmaxf(lx + hx + bc, 0.0f);
                unpack2(acc[i][2], lx, hx); o.z = fmaxf(lx + hx + bc, 0.0f);
                unpack2(acc[i][3], lx, hx); o.w = fmaxf(lx + hx + bc, 0.0f);
                *(float4*)&out[((size_t)(b * R + rec)) * R + s] = o;
            }
        }
    }
}

extern "C" void kernel_launch(void* const* d_in, const int* in_sizes, int n_in,
                              void* d_out, int out_size) {
    (void)in_sizes; (void)n_in; (void)out_size;
    const float* x    = (const float*)d_in[0];  // (16,360,64)
    const float* Wout = (const float*)d_in[1];  // (128,64)
    const float* bout = (const float*)d_in[2];  // (64)
    const float* Wcat = (const float*)d_in[3];  // (64,1)
    const float* bcat = (const float*)d_in[4];  // (1)
    float* out = (float*)d_out;                 // (16,360,360,1) fp32

    k1_uv<<<120, 256>>>(x, Wout, bout);                   // 5760 rows / 48
    k2_pair<<<dim3(6, 8, 16), 256>>>(Wcat, bcat, out);    // 6 send x 8 rec x 16 batch
}

// round 4
// speedup vs baseline: 1.0200x; 1.0200x over previous
#include <cuda_runtime.h>
#include <cstdint>

typedef unsigned long long u64;

#define Bn   16
#define R    360
#define RPAD 384   // padded row length (float2 units) for u/v scratch

// Scratch: u2[b][dpair k][i] = (u[i][2k], u[i][2k+1]) packed fp32x2; same for v (v includes +b_out)
// __device__ globals are zero-initialized: pad region [360,384) stays 0 and is harmless.
__device__ u64 g_u2[Bn * 32 * RPAD];
__device__ u64 g_v2[Bn * 32 * RPAD];

// ---------- packed fp32x2 helpers (sm_100+) ----------
__device__ __forceinline__ u64 pack2(float x, float y) {
    u64 d; asm("mov.b64 %0, {%1, %2};" : "=l"(d) : "f"(x), "f"(y)); return d;
}
__device__ __forceinline__ void unpack2(u64 a, float &x, float &y) {
    asm("mov.b64 {%0, %1}, %2;" : "=f"(x), "=f"(y) : "l"(a));
}
__device__ __forceinline__ void ffma2(u64 &d, u64 a, u64 b) {
    asm("fma.rn.f32x2 %0, %1, %2, %0;" : "+l"(d) : "l"(a), "l"(b));
}
// acc += w * relu(u + v), fully fused packed form
__device__ __forceinline__ void relu_dot2(u64 &acc, u64 u, u64 v, u64 w) {
    asm("{\n\t"
        ".reg .f32 lo, hi;\n\t"
        ".reg .b64 s;\n\t"
        "add.rn.f32x2 s, %1, %2;\n\t"
        "mov.b64 {lo, hi}, s;\n\t"
        "max.f32 lo, lo, 0f00000000;\n\t"
        "max.f32 hi, hi, 0f00000000;\n\t"
        "mov.b64 s, {lo, hi};\n\t"
        "fma.rn.f32x2 %0, s, %3, %0;\n\t"
        "}" : "+l"(acc) : "l"(u), "l"(v), "l"(w));
}

// ============================================================================
// Kernel 1: u = x @ Wout[0:64], v = x @ Wout[64:128] + b_out
// [5760 x 64] @ [64 x 128], fp32x2-packed over k-pairs, 48 rows/block -> 120 blocks.
// Stores transposed: g_u2[b][k][i] = (u[i][2k], u[i][2k+1]).
// ============================================================================
#define K1_ROWS 48

__global__ __launch_bounds__(256, 2) void k1_uv(
    const float* __restrict__ x,      // [5760][64]
    const float* __restrict__ Wout,   // [128][64]
    const float* __restrict__ bout)   // [64]
{
    __shared__ u64 xs[32][K1_ROWS];  // [kpair][row]
    __shared__ u64 Wu[32][64];       // [kpair][d]
    __shared__ u64 Wv[32][64];

    const int t = threadIdx.x;
    const int row0 = blockIdx.x * K1_ROWS;

    // Fill xs
    {
        const u64* x2 = (const u64*)x;   // float2 view (32 per row)
        #pragma unroll
        for (int idx = t; idx < 32 * K1_ROWS; idx += 256) {
            const int p = idx / K1_ROWS;
            const int i = idx - p * K1_ROWS;
            xs[p][i] = x2[(row0 + i) * 32 + p];
        }
    }
    // Fill Wu / Wv (coalesced on d)
    {
        const int c = t & 63, p0 = t >> 6;
        #pragma unroll
        for (int p = p0; p < 32; p += 4) {
            Wu[p][c] = pack2(Wout[(2 * p) * 64 + c],      Wout[(2 * p + 1) * 64 + c]);
            Wv[p][c] = pack2(Wout[(64 + 2 * p) * 64 + c], Wout[(65 + 2 * p) * 64 + c]);
        }
    }
    __syncthreads();

    // Thread tile: 3 rows (stride-16) x 8 cols
    const int rt = t & 15;
    const int ct = t >> 4;            // ct<8 => u cols, ct>=8 => v cols
    const int ccol = (ct & 7) * 8;
    const bool isv = (ct >= 8);
    const u64 (*Ws)[64] = isv ? Wv : Wu;

    u64 acc[3][8];
    #pragma unroll
    for (int ii = 0; ii < 3; ii++)
        #pragma unroll
        for (int j = 0; j < 8; j++) acc[ii][j] = 0ull;

    #pragma unroll 8
    for (int p = 0; p < 32; p++) {
        u64 xv[3];
        #pragma unroll
        for (int ii = 0; ii < 3; ii++) xv[ii] = xs[p][rt + 16 * ii];
        u64 wv[8];
        #pragma unroll
        for (int q = 0; q < 4; q++) {
            ulonglong2 w2 = *(const ulonglong2*)&Ws[p][ccol + 2 * q];
            wv[2 * q] = w2.x; wv[2 * q + 1] = w2.y;
        }
        #pragma unroll
        for (int ii = 0; ii < 3; ii++)
            #pragma unroll
            for (int j = 0; j < 8; j++)
                ffma2(acc[ii][j], xv[ii], wv[j]);   // lo: even-k partial, hi: odd-k partial
    }

    // Epilogue: reduce lo+hi, add b_out for v-half, store transposed pairs
    u64* gdst = isv ? g_v2 : g_u2;
    #pragma unroll
    for (int ii = 0; ii < 3; ii++) {
        const int grow = row0 + rt + 16 * ii;     // [0, 5760)
        const int bb = grow / 360;
        const int i = grow - bb * 360;
        #pragma unroll
        for (int j = 0; j < 8; j += 2) {
            float l0, h0, l1, h1;
            unpack2(acc[ii][j], l0, h0);
            unpack2(acc[ii][j + 1], l1, h1);
            float v0 = l0 + h0, v1 = l1 + h1;
            const int dd = ccol + j;
            if (isv) { v0 += __ldg(&bout[dd]); v1 += __ldg(&bout[dd + 1]); }
            gdst[(bb * 32 + (dd >> 1)) * RPAD + i] = pack2(v0, v1);
        }
    }
}

// ============================================================================
// Kernel 2: out[b,rec,send] = relu( sum_d Wcat[d]*relu(u[send,d]+v[rec,d]) + b_cat )
// CTA tile: 96 send x 64 rec, 256 threads, 6 send x 4 rec = 24 cells/thread.
// ~80 regs, 3 CTAs/SM, grid 4*6*16 = 384 CTAs = single wave on 148 SMs.
// ============================================================================
__global__ __launch_bounds__(256, 3) void k2_pair(
    const float* __restrict__ Wcat,   // [64]
    const float* __restrict__ bcat,   // [1]
    float* __restrict__ out)          // [16*360*360]
{
    __shared__ u64 Us[32][96];    // [dpair][send]
    __shared__ u64 Vs[32][64];    // [dpair][rec]
    __shared__ u64 Ww[32];        // packed Wcat pairs

    const int t = threadIdx.x;
    const int b  = blockIdx.z;
    const int s0 = blockIdx.x * 96;
    const int r0 = blockIdx.y * 64;

    // Fill tiles (coalesced; pad region reads zeros)
    {
        const u64* gub = g_u2 + b * 32 * RPAD + s0;
        #pragma unroll
        for (int idx = t; idx < 32 * 96; idx += 256) {
            const int k = idx / 96;
            const int c = idx - k * 96;
            Us[k][c] = gub[k * RPAD + c];
        }
        const int c = t & 63, k0 = t >> 6;
        const u64* gv = g_v2 + b * 32 * RPAD + r0 + c;
        #pragma unroll
        for (int k = k0; k < 32; k += 4) Vs[k][c] = gv[k * RPAD];
        if (t < 32) Ww[t] = ((const u64*)Wcat)[t];
    }
    __syncthreads();

    const int sx = (t & 15) * 6;   // send base (0..90), 48B-aligned in smem
    const int ry = (t >> 4) * 4;   // rec base  (0..60)

    u64 acc[4][6];
    #pragma unroll
    for (int i = 0; i < 4; i++)
        #pragma unroll
        for (int j = 0; j < 6; j++) acc[i][j] = 0ull;

    #pragma unroll 16
    for (int k = 0; k < 32; k++) {
        const u64 w2 = Ww[k];   // LDS broadcast
        u64 uu[6];
        {
            ulonglong2 ua = *(const ulonglong2*)&Us[k][sx];
            ulonglong2 ub = *(const ulonglong2*)&Us[k][sx + 2];
            ulonglong2 uc = *(const ulonglong2*)&Us[k][sx + 4];
            uu[0] = ua.x; uu[1] = ua.y; uu[2] = ub.x; uu[3] = ub.y;
            uu[4] = uc.x; uu[5] = uc.y;
        }
        u64 vv[4];
        {
            ulonglong2 va = *(const ulonglong2*)&Vs[k][ry];
            ulonglong2 vb = *(const ulonglong2*)&Vs[k][ry + 2];
            vv[0] = va.x; vv[1] = va.y; vv[2] = vb.x; vv[3] = vb.y;
        }
        #pragma unroll
        for (int i = 0; i < 4; i++)
            #pragma unroll
            for (int j = 0; j < 6; j++)
                relu_dot2(acc[i][j], uu[j], vv[i], w2);
    }

    // Epilogue: lo+hi + b_cat, relu, 3x float2 stores per rec row.
    // Tile boundary 360 = s0-aligned per thread (360-288 = 72 = 6*12) -> no straddle.
    const float bc = __ldg(bcat);
    const int s = s0 + sx;
    if (s < R) {
        #pragma unroll
        for (int i = 0; i < 4; i++) {
            const int rec = r0 + ry + i;
            if (rec < R) {
                float* op = &out[((size_t)(b * R + rec)) * R + s];
                #pragma unroll
                for (int j = 0; j < 3; j++) {
                    float lx, hx, l2, h2;
                    unpack2(acc[i][2 * j],     lx, hx);
                    unpack2(acc[i][2 * j + 1], l2, h2);
                    float2 o;
                    o.x = fmaxf(lx + hx + bc, 0.0f);
                    o.y = fmaxf(l2 + h2 + bc, 0.0f);
                    *(float2*)(op + 2 * j) = o;
                }
            }
        }
    }
}

extern "C" void kernel_launch(void* const* d_in, const int* in_sizes, int n_in,
                              void* d_out, int out_size) {
    (void)in_sizes; (void)n_in; (void)out_size;
    const float* x    = (const float*)d_in[0];  // (16,360,64)
    const float* Wout = (const float*)d_in[1];  // (128,64)
    const float* bout = (const float*)d_in[2];  // (64)
    const float* Wcat = (const float*)d_in[3];  // (64,1)
    const float* bcat = (const float*)d_in[4];  // (1)
    float* out = (float*)d_out;                 // (16,360,360,1) fp32

    k1_uv<<<120, 256>>>(x, Wout, bout);                   // 5760 rows / 48
    k2_pair<<<dim3(4, 6, 16), 256>>>(Wcat, bcat, out);    // 4 send x 6 rec x 16 batch
}

// round 6
// speedup vs baseline: 1.0850x; 1.0638x over previous
#include <cuda_runtime.h>
#include <cstdint>

typedef unsigned long long u64;

#define Bn   16
#define R    360
#define RPAD 384   // padded row length (float2 units) for u/v scratch

// Scratch: u2[b][dpair k][i] = (u[i][2k], u[i][2k+1]) packed fp32x2; same for v (v includes +b_out)
__device__ u64 g_u2[Bn * 32 * RPAD];
__device__ u64 g_v2[Bn * 32 * RPAD];

// ---------- packed fp32x2 helpers (sm_100+) ----------
__device__ __forceinline__ u64 pack2(float x, float y) {
    u64 d; asm("mov.b64 %0, {%1, %2};" : "=l"(d) : "f"(x), "f"(y)); return d;
}
__device__ __forceinline__ void unpack2(u64 a, float &x, float &y) {
    asm("mov.b64 {%0, %1}, %2;" : "=f"(x), "=f"(y) : "l"(a));
}
__device__ __forceinline__ void ffma2(u64 &d, u64 a, u64 b) {
    asm("fma.rn.f32x2 %0, %1, %2, %0;" : "+l"(d) : "l"(a), "l"(b));
}
// acc += w * |u + v| : FADD2 + 2x in-place LOP3 (packed abs) + FFMA2. No movs.
__device__ __forceinline__ void absdot2(u64 &acc, u64 u, u64 v, u64 w) {
    u64 s;
    asm("add.rn.f32x2 %0, %1, %2;" : "=l"(s) : "l"(u), "l"(v));
    s &= 0x7FFFFFFF7FFFFFFFull;   // packed abs: clears both sign bits, stays in the pair
    ffma2(acc, s, w);
}

// ============================================================================
// Kernel 1: u = x @ Wout[0:64], v = x @ Wout[64:128] + b_out  (R2-proven)
// ============================================================================
#define K1_ROWS 48

__global__ __launch_bounds__(256, 2) void k1_uv(
    const float* __restrict__ x,      // [5760][64]
    const float* __restrict__ Wout,   // [128][64]
    const float* __restrict__ bout)   // [64]
{
    __shared__ u64 xs[32][K1_ROWS];  // [kpair][row]
    __shared__ u64 Wu[32][64];       // [kpair][d]
    __shared__ u64 Wv[32][64];

    const int t = threadIdx.x;
    const int row0 = blockIdx.x * K1_ROWS;

    {
        const u64* x2 = (const u64*)x;   // float2 view (32 per row)
        #pragma unroll
        for (int idx = t; idx < 32 * K1_ROWS; idx += 256) {
            const int p = idx / K1_ROWS;
            const int i = idx - p * K1_ROWS;
            xs[p][i] = x2[(row0 + i) * 32 + p];
        }
    }
    {
        const int c = t & 63, p0 = t >> 6;
        #pragma unroll
        for (int p = p0; p < 32; p += 4) {
            Wu[p][c] = pack2(Wout[(2 * p) * 64 + c],      Wout[(2 * p + 1) * 64 + c]);
            Wv[p][c] = pack2(Wout[(64 + 2 * p) * 64 + c], Wout[(65 + 2 * p) * 64 + c]);
        }
    }
    __syncthreads();

    const int rt = t & 15;
    const int ct = t >> 4;
    const int ccol = (ct & 7) * 8;
    const bool isv = (ct >= 8);
    const u64 (*Ws)[64] = isv ? Wv : Wu;

    u64 acc[3][8];
    #pragma unroll
    for (int ii = 0; ii < 3; ii++)
        #pragma unroll
        for (int j = 0; j < 8; j++) acc[ii][j] = 0ull;

    #pragma unroll 8
    for (int p = 0; p < 32; p++) {
        u64 xv[3];
        #pragma unroll
        for (int ii = 0; ii < 3; ii++) xv[ii] = xs[p][rt + 16 * ii];
        u64 wv[8];
        #pragma unroll
        for (int q = 0; q < 4; q++) {
            ulonglong2 w2 = *(const ulonglong2*)&Ws[p][ccol + 2 * q];
            wv[2 * q] = w2.x; wv[2 * q + 1] = w2.y;
        }
        #pragma unroll
        for (int ii = 0; ii < 3; ii++)
            #pragma unroll
            for (int j = 0; j < 8; j++)
                ffma2(acc[ii][j], xv[ii], wv[j]);
    }

    u64* gdst = isv ? g_v2 : g_u2;
    #pragma unroll
    for (int ii = 0; ii < 3; ii++) {
        const int grow = row0 + rt + 16 * ii;
        const int bb = grow / 360;
        const int i = grow - bb * 360;
        #pragma unroll
        for (int j = 0; j < 8; j += 2) {
            float l0, h0, l1, h1;
            unpack2(acc[ii][j], l0, h0);
            unpack2(acc[ii][j + 1], l1, h1);
            float v0 = l0 + h0, v1 = l1 + h1;
            const int dd = ccol + j;
            if (isv) { v0 += __ldg(&bout[dd]); v1 += __ldg(&bout[dd + 1]); }
            gdst[(bb * 32 + (dd >> 1)) * RPAD + i] = pack2(v0, v1);
        }
    }
}

// ============================================================================
// Kernel 2: out[b,r,s] = relu( C_s + D_r + sum_d 0.5*w_d*|u_sd+v_rd| + b_cat )
// where C_s = sum_d 0.5*w_d*u_sd, D_r = sum_d 0.5*w_d*v_rd (per-tile precompute).
// 64x64 tile, 256 threads, 4x4 cells/thread, grid 576.
// ============================================================================
__global__ __launch_bounds__(256, 4) void k2_pair(
    const float* __restrict__ Wcat,   // [64]
    const float* __restrict__ bcat,   // [1]
    float* __restrict__ out)          // [16*360*360]
{
    __shared__ u64 Us[32][64];    // [dpair][send]
    __shared__ u64 Vs[32][64];    // [dpair][rec]
    __shared__ u64 Ww[32];        // packed 0.5*Wcat pairs
    __shared__ float Cs[64];      // C per send
    __shared__ float Ds[64];      // D per rec

    const int t = threadIdx.x;
    const int b  = blockIdx.z;
    const int s0 = blockIdx.x * 64;
    const int r0 = blockIdx.y * 64;

    // Fill tiles (coalesced 512B rows; pad region [360,384) holds zeros)
    {
        const int c = t & 63, k0 = t >> 6;
        const u64* gu = g_u2 + b * 32 * RPAD + s0 + c;
        const u64* gv = g_v2 + b * 32 * RPAD + r0 + c;
        #pragma unroll
        for (int k = k0; k < 32; k += 4) {
            Us[k][c] = gu[k * RPAD];
            Vs[k][c] = gv[k * RPAD];
        }
        if (t < 32) {
            u64 w = ((const u64*)Wcat)[t];
            const u64 half2 = 0x3F0000003F000000ull;   // (0.5f, 0.5f)
            asm("mul.rn.f32x2 %0, %0, %1;" : "+l"(w) : "l"(half2));
            Ww[t] = w;
        }
    }
    __syncthreads();

    // Precompute C_s (warps 0-1) and D_r (warps 2-3): ~100 instrs on 128 threads
    if (t < 128) {
        const int c = t & 63;
        const bool isD = (t >= 64);
        u64 a = 0ull;
        #pragma unroll 8
        for (int k = 0; k < 32; k++) {
            const u64 val = isD ? Vs[k][c] : Us[k][c];
            ffma2(a, val, Ww[k]);
        }
        float lo, hi; unpack2(a, lo, hi);
        if (isD) Ds[c] = lo + hi; else Cs[c] = lo + hi;
    }
    __syncthreads();

    const int sx = (t & 15) * 4;   // send base
    const int ry = (t >> 4) * 4;   // rec base

    u64 acc[4][4];
    #pragma unroll
    for (int i = 0; i < 4; i++)
        #pragma unroll
        for (int j = 0; j < 4; j++) acc[i][j] = 0ull;

    #pragma unroll 8
    for (int k = 0; k < 32; k++) {
        const u64 w2 = Ww[k];   // LDS broadcast (0.5*w packed)
        u64 uu[4];
        {
            ulonglong2 ua = *(const ulonglong2*)&Us[k][sx];
            ulonglong2 ub = *(const ulonglong2*)&Us[k][sx + 2];
            uu[0] = ua.x; uu[1] = ua.y; uu[2] = ub.x; uu[3] = ub.y;
        }
        u64 vv[4];
        {
            ulonglong2 va = *(const ulonglong2*)&Vs[k][ry];
            ulonglong2 vb = *(const ulonglong2*)&Vs[k][ry + 2];
            vv[0] = va.x; vv[1] = va.y; vv[2] = vb.x; vv[3] = vb.y;
        }
        #pragma unroll
        for (int i = 0; i < 4; i++)
            #pragma unroll
            for (int j = 0; j < 4; j++)
                absdot2(acc[i][j], uu[j], vv[i], w2);
    }

    // Epilogue: val = acc_lo+acc_hi + C_s + D_r + bc -> relu -> float4 store
    const float bc = __ldg(bcat);
    float cv[4];
    #pragma unroll
    for (int j = 0; j < 4; j++) cv[j] = Cs[sx + j] + bc;   // fold bias into C
    const int s = s0 + sx;
    if (s < R) {
        #pragma unroll
        for (int i = 0; i < 4; i++) {
            const int rec = r0 + ry + i;
            if (rec < R) {
                const float dr = Ds[ry + i];
                float4 o;
                float lx, hx;
                unpack2(acc[i][0], lx, hx); o.x = fmaxf(lx + hx + cv[0] + dr, 0.0f);
                unpack2(acc[i][1], lx, hx); o.y = fmaxf(lx + hx + cv[1] + dr, 0.0f);
                unpack2(acc[i][2], lx, hx); o.z = fmaxf(lx + hx + cv[2] + dr, 0.0f);
                unpack2(acc[i][3], lx, hx); o.w = fmaxf(lx + hx + cv[3] + dr, 0.0f);
                *(float4*)&out[((size_t)(b * R + rec)) * R + s] = o;
            }
        }
    }
}

extern "C" void kernel_launch(void* const* d_in, const int* in_sizes, int n_in,
                              void* d_out, int out_size) {
    (void)in_sizes; (void)n_in; (void)out_size;
    const float* x    = (const float*)d_in[0];  // (16,360,64)
    const float* Wout = (const float*)d_in[1];  // (128,64)
    const float* bout = (const float*)d_in[2];  // (64)
    const float* Wcat = (const float*)d_in[3];  // (64,1)
    const float* bcat = (const float*)d_in[4];  // (1)
    float* out = (float*)d_out;                 // (16,360,360,1) fp32

    k1_uv<<<120, 256>>>(x, Wout, bout);                   // 5760 rows / 48
    k2_pair<<<dim3(6, 6, 16), 256>>>(Wcat, bcat, out);    // 6 send x 6 rec x 16 batch
}

// round 7
// speedup vs baseline: 1.1737x; 1.0817x over previous
#include <cuda_runtime.h>
#include <cstdint>

typedef unsigned long long u64;

#define Bn   16
#define R    360
#define RPAD 384   // padded row length (float2 units) for u/v scratch

// Scratch: u2[b][dpair k][i] = (u[i][2k], u[i][2k+1]) packed fp32x2; same for v (v includes +b_out)
// __device__ globals are zero-initialized; pad [360,384) stays zero (k1 never writes it).
__device__ u64 g_u2[Bn * 32 * RPAD];
__device__ u64 g_v2[Bn * 32 * RPAD];

// ---------- packed fp32x2 helpers (sm_100+) ----------
__device__ __forceinline__ u64 pack2(float x, float y) {
    u64 d; asm("mov.b64 %0, {%1, %2};" : "=l"(d) : "f"(x), "f"(y)); return d;
}
__device__ __forceinline__ void unpack2(u64 a, float &x, float &y) {
    asm("mov.b64 {%0, %1}, %2;" : "=f"(x), "=f"(y) : "l"(a));
}
__device__ __forceinline__ void ffma2(u64 &d, u64 a, u64 b) {
    asm("fma.rn.f32x2 %0, %1, %2, %0;" : "+l"(d) : "l"(a), "l"(b));
}
// acc += w * relu(u+v): R2-proven form (ptxas colors {lo,hi} onto the pair, no movs)
__device__ __forceinline__ void relu_dot2(u64 &acc, u64 u, u64 v, u64 w) {
    u64 s;
    asm("add.rn.f32x2 %0, %1, %2;" : "=l"(s) : "l"(u), "l"(v));
    float lo, hi; unpack2(s, lo, hi);
    lo = fmaxf(lo, 0.0f); hi = fmaxf(hi, 0.0f);
    s = pack2(lo, hi);
    ffma2(acc, s, w);
}

// ============================================================================
// Kernel 1: u = x @ Wout[0:64], v = x @ Wout[64:128] + b_out  (R2-proven)
// ============================================================================
#define K1_ROWS 48

__global__ __launch_bounds__(256, 2) void k1_uv(
    const float* __restrict__ x,      // [5760][64]
    const float* __restrict__ Wout,   // [128][64]
    const float* __restrict__ bout)   // [64]
{
    __shared__ u64 xs[32][K1_ROWS];  // [kpair][row]
    __shared__ u64 Wu[32][64];       // [kpair][d]
    __shared__ u64 Wv[32][64];

    const int t = threadIdx.x;
    const int row0 = blockIdx.x * K1_ROWS;

    {
        const u64* x2 = (const u64*)x;   // float2 view (32 per row)
        #pragma unroll
        for (int idx = t; idx < 32 * K1_ROWS; idx += 256) {
            const int p = idx / K1_ROWS;
            const int i = idx - p * K1_ROWS;
            xs[p][i] = x2[(row0 + i) * 32 + p];
        }
    }
    {
        const int c = t & 63, p0 = t >> 6;
        #pragma unroll
        for (int p = p0; p < 32; p += 4) {
            Wu[p][c] = pack2(Wout[(2 * p) * 64 + c],      Wout[(2 * p + 1) * 64 + c]);
            Wv[p][c] = pack2(Wout[(64 + 2 * p) * 64 + c], Wout[(65 + 2 * p) * 64 + c]);
        }
    }
    __syncthreads();

    const int rt = t & 15;
    const int ct = t >> 4;
    const int ccol = (ct & 7) * 8;
    const bool isv = (ct >= 8);
    const u64 (*Ws)[64] = isv ? Wv : Wu;

    u64 acc[3][8];
    #pragma unroll
    for (int ii = 0; ii < 3; ii++)
        #pragma unroll
        for (int j = 0; j < 8; j++) acc[ii][j] = 0ull;

    #pragma unroll 8
    for (int p = 0; p < 32; p++) {
        u64 xv[3];
        #pragma unroll
        for (int ii = 0; ii < 3; ii++) xv[ii] = xs[p][rt + 16 * ii];
        u64 wv[8];
        #pragma unroll
        for (int q = 0; q < 4; q++) {
            ulonglong2 w2 = *(const ulonglong2*)&Ws[p][ccol + 2 * q];
            wv[2 * q] = w2.x; wv[2 * q + 1] = w2.y;
        }
        #pragma unroll
        for (int ii = 0; ii < 3; ii++)
            #pragma unroll
            for (int j = 0; j < 8; j++)
                ffma2(acc[ii][j], xv[ii], wv[j]);
    }

    u64* gdst = isv ? g_v2 : g_u2;
    #pragma unroll
    for (int ii = 0; ii < 3; ii++) {
        const int grow = row0 + rt + 16 * ii;
        const int bb = grow / 360;
        const int i = grow - bb * 360;
        #pragma unroll
        for (int j = 0; j < 8; j += 2) {
            float l0, h0, l1, h1;
            unpack2(acc[ii][j], l0, h0);
            unpack2(acc[ii][j + 1], l1, h1);
            float v0 = l0 + h0, v1 = l1 + h1;
            const int dd = ccol + j;
            if (isv) { v0 += __ldg(&bout[dd]); v1 += __ldg(&bout[dd + 1]); }
            gdst[(bb * 32 + (dd >> 1)) * RPAD + i] = pack2(v0, v1);
        }
    }
}

// ============================================================================
// Kernel 2: out[b,rec,send] = relu( sum_d Wcat[d]*relu(u[send,d]+v[rec,d]) + b_cat )
// 64x64 tile, 256 threads. Thread tile: 2 sends (lane-contiguous) x 8 recs (warp).
// uu: ONE conflict-free LDS.128/k (lane-seq 16B). vv: 4 broadcast LDS.128/k.
// ============================================================================
__global__ __launch_bounds__(256, 4) void k2_pair(
    const float* __restrict__ Wcat,   // [64]
    const float* __restrict__ bcat,   // [1]
    float* __restrict__ out)          // [16*360*360]
{
    __shared__ u64 Us[32][64];    // [dpair][send]
    __shared__ u64 Vs[32][64];    // [dpair][rec]
    __shared__ u64 Ww[32];        // packed Wcat pairs

    const int t = threadIdx.x;
    const int b  = blockIdx.z;
    const int s0 = blockIdx.x * 64;
    const int r0 = blockIdx.y * 64;

    // Fill tiles (coalesced 512B rows; pad region reads zeros)
    {
        const int c = t & 63, k0 = t >> 6;
        const u64* gu = g_u2 + b * 32 * RPAD + s0 + c;
        const u64* gv = g_v2 + b * 32 * RPAD + r0 + c;
        #pragma unroll
        for (int k = k0; k < 32; k += 4) {
            Us[k][c] = gu[k * RPAD];
            Vs[k][c] = gv[k * RPAD];
        }
        if (t < 32) Ww[t] = ((const u64*)Wcat)[t];
    }
    __syncthreads();

    const int lane = t & 31;       // sends 2*lane, 2*lane+1
    const int wg   = t >> 5;       // recs 8*wg .. 8*wg+7

    u64 acc[8][2];
    #pragma unroll
    for (int i = 0; i < 8; i++) { acc[i][0] = 0ull; acc[i][1] = 0ull; }

    #pragma unroll 8
    for (int k = 0; k < 32; k++) {
        const u64 w2 = Ww[k];                           // broadcast LDS.64
        ulonglong2 ua = *(const ulonglong2*)&Us[k][2 * lane];   // conflict-free LDS.128
        u64 vv[8];
        #pragma unroll
        for (int q = 0; q < 4; q++) {                   // broadcast LDS.128 x4
            ulonglong2 va = *(const ulonglong2*)&Vs[k][8 * wg + 2 * q];
            vv[2 * q] = va.x; vv[2 * q + 1] = va.y;
        }
        #pragma unroll
        for (int i = 0; i < 8; i++) {
            relu_dot2(acc[i][0], ua.x, vv[i], w2);
            relu_dot2(acc[i][1], ua.y, vv[i], w2);
        }
    }

    // Epilogue: lo+hi + b_cat, relu, float2 stores (256B coalesced per rec row)
    const float bc = __ldg(bcat);
    const int s = s0 + 2 * lane;
    if (s < R) {
        #pragma unroll
        for (int i = 0; i < 8; i++) {
            const int rec = r0 + 8 * wg + i;
            if (rec < R) {
                float l0, h0, l1, h1;
                unpack2(acc[i][0], l0, h0);
                unpack2(acc[i][1], l1, h1);
                float2 o;
                o.x = fmaxf(l0 + h0 + bc, 0.0f);
                o.y = fmaxf(l1 + h1 + bc, 0.0f);
                *(float2*)&out[((size_t)(b * R + rec)) * R + s] = o;
            }
        }
    }
}

extern "C" void kernel_launch(void* const* d_in, const int* in_sizes, int n_in,
                              void* d_out, int out_size) {
    (void)in_sizes; (void)n_in; (void)out_size;
    const float* x    = (const float*)d_in[0];  // (16,360,64)
    const float* Wout = (const float*)d_in[1];  // (128,64)
    const float* bout = (const float*)d_in[2];  // (64)
    const float* Wcat = (const float*)d_in[3];  // (64,1)
    const float* bcat = (const float*)d_in[4];  // (1)
    float* out = (float*)d_out;                 // (16,360,360,1) fp32

    k1_uv<<<120, 256>>>(x, Wout, bout);                   // 5760 rows / 48
    k2_pair<<<dim3(6, 6, 16), 256>>>(Wcat, bcat, out);    // 6 send x 6 rec x 16 batch
}